// round 10
// baseline (speedup 1.0000x reference)
#include <cuda_runtime.h>
#include <cstdint>

#define NUM_RELS 500
#define N_NODES  200000
#define ENT_DIM  128

// Per-relation scalars: c0 = [S_pp, 2*S_pr, 2*S_p, S_rr], c1 = 2*S_r
__device__ float4 g_rel_c0[NUM_RELS];
__device__ float  g_rel_c1[NUM_RELS];
// Per-node scalars: x = emb_p . emb,  y = sum(emb)
__device__ float2 g_node_h[N_NODES];
__device__ float2 g_node_t[N_NODES];

__device__ __forceinline__ float warp_sum(float v) {
    #pragma unroll
    for (int o = 16; o > 0; o >>= 1)
        v += __shfl_xor_sync(0xFFFFFFFFu, v, o);
    return v;
}

// Fused precompute (1 node per warp, one-shot — best measured config):
//   warp <  N_NODES           : per-node scalars for all 4 entity tables
//   warp in [N_NODES, +RELS)  : per-relation scalars
__global__ __launch_bounds__(256)
void precompute_kernel(const float* __restrict__ head_emb,
                       const float* __restrict__ head_emb_p,
                       const float* __restrict__ tail_emb,
                       const float* __restrict__ tail_emb_p,
                       const float* __restrict__ rel_emb,
                       const float* __restrict__ rel_emb_p) {
    int warp = (blockIdx.x * blockDim.x + threadIdx.x) >> 5;
    int lane = threadIdx.x & 31;

    if (warp < N_NODES) {
        int node = warp;
        size_t off = (size_t)node * ENT_DIM + lane * 4;

        // Streaming loads: read-once data, evict-first.
        float4 h  = __ldcs(reinterpret_cast<const float4*>(head_emb   + off));
        float4 hp = __ldcs(reinterpret_cast<const float4*>(head_emb_p + off));
        float4 t  = __ldcs(reinterpret_cast<const float4*>(tail_emb   + off));
        float4 tp = __ldcs(reinterpret_cast<const float4*>(tail_emb_p + off));

        float ah = hp.x*h.x + hp.y*h.y + hp.z*h.z + hp.w*h.w;
        float bh = h.x + h.y + h.z + h.w;
        float at = tp.x*t.x + tp.y*t.y + tp.z*t.z + tp.w*t.w;
        float bt = t.x + t.y + t.z + t.w;

        ah = warp_sum(ah);
        bh = warp_sum(bh);
        at = warp_sum(at);
        bt = warp_sum(bt);

        if (lane == 0) {
            g_node_h[node] = make_float2(ah, bh);
            g_node_t[node] = make_float2(at, bt);
        }
    } else if (warp < N_NODES + NUM_RELS) {
        int rel = warp - N_NODES;
        const float4* r4 = reinterpret_cast<const float4*>(rel_emb   + (size_t)rel * ENT_DIM);
        const float4* p4 = reinterpret_cast<const float4*>(rel_emb_p + (size_t)rel * ENT_DIM);
        float4 q = __ldcs(r4 + lane);
        float4 p = __ldcs(p4 + lane);

        float s_pp = p.x*p.x + p.y*p.y + p.z*p.z + p.w*p.w;
        float s_pr = p.x*q.x + p.y*q.y + p.z*q.z + p.w*q.w;
        float s_p  = p.x + p.y + p.z + p.w;
        float s_rr = q.x*q.x + q.y*q.y + q.z*q.z + q.w*q.w;
        float s_r  = q.x + q.y + q.z + q.w;

        s_pp = warp_sum(s_pp);
        s_pr = warp_sum(s_pr);
        s_p  = warp_sum(s_p);
        s_rr = warp_sum(s_rr);
        s_r  = warp_sum(s_r);

        if (lane == 0) {
            // Fold the 2x factors so the score kernel does pure FMA.
            g_rel_c0[rel] = make_float4(s_pp, 2.0f*s_pr, 2.0f*s_p, s_rr);
            g_rel_c1[rel] = 2.0f*s_r;
        }
    }
}

// One thread per batch row — lowest measured config (19 regs, no smem,
// no sync, max occupancy). All gathers issued before dependent math;
// rel tables (10KB) L1-resident, node tables (3.2MB) L2-resident.
__global__ __launch_bounds__(256)
void transd_score_kernel(const int* __restrict__ head_idx,
                         const int* __restrict__ tail_idx,
                         const int* __restrict__ rel_idx,
                         float* __restrict__ out,
                         int B) {
    int i = blockIdx.x * blockDim.x + threadIdx.x;
    if (i >= B) return;

    int hi = head_idx[i];
    int ti = tail_idx[i];
    int ri = rel_idx[i];

    float2 hc = __ldg(&g_node_h[hi]);
    float2 tc = __ldg(&g_node_t[ti]);
    float4 c0 = __ldg(&g_rel_c0[ri]);
    float  c1 = __ldg(&g_rel_c1[ri]);

    float a = hc.x - tc.x;   // h_p.h - t_p.t
    float b = hc.y - tc.y;   // sum(h) - sum(t)

    // score = a^2*S_pp + a*(2S_pr) + ab*(2S_p) + S_rr + b*(2S_r) + D*b^2
    out[i] = a*a*c0.x + a*c0.y + a*b*c0.z
           + c0.w + b*c1 + (float)ENT_DIM * b*b;
}

extern "C" void kernel_launch(void* const* d_in, const int* in_sizes, int n_in,
                              void* d_out, int out_size) {
    const float* head_emb   = (const float*)d_in[0];
    const float* head_emb_p = (const float*)d_in[1];
    const float* tail_emb   = (const float*)d_in[2];
    const float* tail_emb_p = (const float*)d_in[3];
    const float* rel_emb    = (const float*)d_in[4];
    const float* rel_emb_p  = (const float*)d_in[5];
    const int*   head_idx   = (const int*)d_in[6];
    const int*   tail_idx   = (const int*)d_in[7];
    const int*   rel_idx    = (const int*)d_in[8];
    float* out = (float*)d_out;

    int B = in_sizes[6];

    // Fused per-node + per-relation precompute (streams all tables once).
    {
        int threads = 256;                 // 8 warps/block
        long long warps = (long long)N_NODES + NUM_RELS;
        int blocks = (int)((warps * 32 + threads - 1) / threads);
        precompute_kernel<<<blocks, threads>>>(head_emb, head_emb_p,
                                               tail_emb, tail_emb_p,
                                               rel_emb, rel_emb_p);
    }

    // Closed-form score, one thread per row.
    {
        int threads = 256;
        int blocks = (B + threads - 1) / threads;
        transd_score_kernel<<<blocks, threads>>>(head_idx, tail_idx, rel_idx,
                                                 out, B);
    }
}

// round 11
// speedup vs baseline: 1.0061x; 1.0061x over previous
#include <cuda_runtime.h>
#include <cstdint>

#define NUM_RELS 500
#define N_NODES  200000
#define ENT_DIM  128

// Per-relation scalars: c0 = [S_pp, 2*S_pr, 2*S_p, S_rr], c1 = 2*S_r
__device__ float4 g_rel_c0[NUM_RELS];
__device__ float  g_rel_c1[NUM_RELS];
// Per-node scalars: x = emb_p . emb,  y = sum(emb)
__device__ float2 g_node_h[N_NODES];
__device__ float2 g_node_t[N_NODES];

__device__ __forceinline__ float warp_sum(float v) {
    #pragma unroll
    for (int o = 16; o > 0; o >>= 1)
        v += __shfl_xor_sync(0xFFFFFFFFu, v, o);
    return v;
}

// Fused precompute (1 node per warp, one-shot — best measured config):
//   warp <  N_NODES           : per-node scalars for all 4 entity tables
//   warp in [N_NODES, +RELS)  : per-relation scalars
__global__ __launch_bounds__(256)
void precompute_kernel(const float* __restrict__ head_emb,
                       const float* __restrict__ head_emb_p,
                       const float* __restrict__ tail_emb,
                       const float* __restrict__ tail_emb_p,
                       const float* __restrict__ rel_emb,
                       const float* __restrict__ rel_emb_p) {
    int warp = (blockIdx.x * blockDim.x + threadIdx.x) >> 5;
    int lane = threadIdx.x & 31;

    if (warp < N_NODES) {
        int node = warp;
        size_t off = (size_t)node * ENT_DIM + lane * 4;

        // Streaming loads: read-once data, evict-first.
        float4 h  = __ldcs(reinterpret_cast<const float4*>(head_emb   + off));
        float4 hp = __ldcs(reinterpret_cast<const float4*>(head_emb_p + off));
        float4 t  = __ldcs(reinterpret_cast<const float4*>(tail_emb   + off));
        float4 tp = __ldcs(reinterpret_cast<const float4*>(tail_emb_p + off));

        float ah = hp.x*h.x + hp.y*h.y + hp.z*h.z + hp.w*h.w;
        float bh = h.x + h.y + h.z + h.w;
        float at = tp.x*t.x + tp.y*t.y + tp.z*t.z + tp.w*t.w;
        float bt = t.x + t.y + t.z + t.w;

        ah = warp_sum(ah);
        bh = warp_sum(bh);
        at = warp_sum(at);
        bt = warp_sum(bt);

        if (lane == 0) {
            g_node_h[node] = make_float2(ah, bh);
            g_node_t[node] = make_float2(at, bt);
        }
    } else if (warp < N_NODES + NUM_RELS) {
        int rel = warp - N_NODES;
        const float4* r4 = reinterpret_cast<const float4*>(rel_emb   + (size_t)rel * ENT_DIM);
        const float4* p4 = reinterpret_cast<const float4*>(rel_emb_p + (size_t)rel * ENT_DIM);
        float4 q = __ldcs(r4 + lane);
        float4 p = __ldcs(p4 + lane);

        float s_pp = p.x*p.x + p.y*p.y + p.z*p.z + p.w*p.w;
        float s_pr = p.x*q.x + p.y*q.y + p.z*q.z + p.w*q.w;
        float s_p  = p.x + p.y + p.z + p.w;
        float s_rr = q.x*q.x + q.y*q.y + q.z*q.z + q.w*q.w;
        float s_r  = q.x + q.y + q.z + q.w;

        s_pp = warp_sum(s_pp);
        s_pr = warp_sum(s_pr);
        s_p  = warp_sum(s_p);
        s_rr = warp_sum(s_rr);
        s_r  = warp_sum(s_r);

        if (lane == 0) {
            // Fold the 2x factors so the score kernel does pure FMA.
            g_rel_c0[rel] = make_float4(s_pp, 2.0f*s_pr, 2.0f*s_p, s_rr);
            g_rel_c1[rel] = 2.0f*s_r;
        }
    }
}

// Two rows per thread, no smem, low regs: int2 index loads, 4 independent
// node gathers + 4 rel-constant loads in flight before any dependent math.
__global__ __launch_bounds__(256)
void transd_score_kernel(const int* __restrict__ head_idx,
                         const int* __restrict__ tail_idx,
                         const int* __restrict__ rel_idx,
                         float* __restrict__ out,
                         int B) {
    int t = blockIdx.x * blockDim.x + threadIdx.x;
    int base = t * 2;
    if (base + 1 < B) {
        int2 hi = __ldcs(reinterpret_cast<const int2*>(head_idx + base));
        int2 ti = __ldcs(reinterpret_cast<const int2*>(tail_idx + base));
        int2 ri = __ldcs(reinterpret_cast<const int2*>(rel_idx  + base));

        // All gathers issued before dependent math.
        float2 h0 = __ldg(&g_node_h[hi.x]);
        float2 h1 = __ldg(&g_node_h[hi.y]);
        float2 t0 = __ldg(&g_node_t[ti.x]);
        float2 t1 = __ldg(&g_node_t[ti.y]);
        float4 c00 = __ldg(&g_rel_c0[ri.x]);
        float4 c01 = __ldg(&g_rel_c0[ri.y]);
        float  c10 = __ldg(&g_rel_c1[ri.x]);
        float  c11 = __ldg(&g_rel_c1[ri.y]);

        float2 res;
        {
            float a = h0.x - t0.x, b = h0.y - t0.y;
            res.x = a*a*c00.x + a*c00.y + a*b*c00.z
                  + c00.w + b*c10 + (float)ENT_DIM * b*b;
        }
        {
            float a = h1.x - t1.x, b = h1.y - t1.y;
            res.y = a*a*c01.x + a*c01.y + a*b*c01.z
                  + c01.w + b*c11 + (float)ENT_DIM * b*b;
        }
        __stcs(reinterpret_cast<float2*>(out + base), res);
    } else {
        for (int i = base; i < B; i++) {
            float2 hc = __ldg(&g_node_h[head_idx[i]]);
            float2 tc = __ldg(&g_node_t[tail_idx[i]]);
            float4 c0 = __ldg(&g_rel_c0[rel_idx[i]]);
            float  c1 = __ldg(&g_rel_c1[rel_idx[i]]);
            float a = hc.x - tc.x, b = hc.y - tc.y;
            out[i] = a*a*c0.x + a*c0.y + a*b*c0.z
                   + c0.w + b*c1 + (float)ENT_DIM * b*b;
        }
    }
}

extern "C" void kernel_launch(void* const* d_in, const int* in_sizes, int n_in,
                              void* d_out, int out_size) {
    const float* head_emb   = (const float*)d_in[0];
    const float* head_emb_p = (const float*)d_in[1];
    const float* tail_emb   = (const float*)d_in[2];
    const float* tail_emb_p = (const float*)d_in[3];
    const float* rel_emb    = (const float*)d_in[4];
    const float* rel_emb_p  = (const float*)d_in[5];
    const int*   head_idx   = (const int*)d_in[6];
    const int*   tail_idx   = (const int*)d_in[7];
    const int*   rel_idx    = (const int*)d_in[8];
    float* out = (float*)d_out;

    int B = in_sizes[6];

    // Fused per-node + per-relation precompute (streams all tables once).
    {
        int threads = 256;                 // 8 warps/block
        long long warps = (long long)N_NODES + NUM_RELS;
        int blocks = (int)((warps * 32 + threads - 1) / threads);
        precompute_kernel<<<blocks, threads>>>(head_emb, head_emb_p,
                                               tail_emb, tail_emb_p,
                                               rel_emb, rel_emb_p);
    }

    // Closed-form score, two rows per thread.
    {
        int threads = 256;
        int rows_per_block = threads * 2;
        int blocks = (B + rows_per_block - 1) / rows_per_block;
        transd_score_kernel<<<blocks, threads>>>(head_idx, tail_idx, rel_idx,
                                                 out, B);
    }
}